// round 11
// baseline (speedup 1.0000x reference)
#include <cuda_runtime.h>
#include <cuda_bf16.h>
#include <cstdint>

// Problem shapes (fixed by the dataset)
#define S_LEN 2048
#define BATCH 16
#define DDIM  2048

// Quarter pipeline: stage1 output o-range == stage2 reduction d-range.
#define NQ    4
#define QDIM  (DDIM / NQ)          // 512
#define NCHQ  2                    // o-chunks per quarter
#define OCH   256                  // o rows per chunk (1 per thread @256thr)
#define KS    32                   // k-splits per (quarter, chunk)
#define KCH   (DDIM / KS)          // 64 d per stage1 block
#define SUBK  32                   // d per smem subtile
#define NSUB  (KCH / SUBK)         // 2
#define WPAD  33                   // sW bank = (t + d) % 32 -> conflict-free
#define SPAD  20                   // sS row stride (80B, 16B-aligned LDS.128)

#define NB_S1 (NQ * NCHQ * KS)     // 256 producer blocks (bids 0..255)
#define NS2   ((S_LEN / 16) * BATCH) // 2048 consumer blocks
#define NB    (NB_S1 + NS2)

// Scratch (device globals: allocation-free). All counters zero-init and
// self-resetting at the end of each launch -> graph-replay safe.
__device__ float g_part[NQ][NCHQ][KS][OCH][BATCH];  // 4 MB
__device__ float g_altered[BATCH * DDIM];           // [b][o], 128 KB
__device__ int   g_cnt[NQ * NCHQ];
__device__ int   g_flag[NQ];
__device__ int   g_s2cnt;

__device__ __forceinline__ void ffma2(uint64_t& d, uint64_t a, uint64_t b) {
    asm("fma.rn.f32x2 %0, %1, %2, %0;" : "+l"(d) : "l"(a), "l"(b));
}

// ---------------------------------------------------------------------------
// ONE fused kernel. Blocks 0..255 are stage1 producers (scheduled first in
// wave 1 by bid order; wave-1 capacity ~590 blocks >> 256, so producers can
// never be starved by spinning consumers -> no deadlock). Blocks 256+ are
// stage2 consumers gated per-quarter on g_flag.
// ---------------------------------------------------------------------------
__global__ void __launch_bounds__(256)
attender_fused(const float* __restrict__ state,
               const float* __restrict__ W,
               const float* __restrict__ bias,
               const float* __restrict__ enc,
               float* __restrict__ out)
{
    __shared__ union {
        struct { float sW[OCH][WPAD]; float sS[SUBK][SPAD]; } s1;  // 36.3 KB
        float alt[QDIM];                                            // 2 KB
    } sm;
    __shared__ int s_tk;

    const int t   = threadIdx.x;
    const int bid = blockIdx.x;

    if (bid < NB_S1) {
        // ================= Stage 1 producer =================
        const int q     = bid >> 6;           // quarter
        const int ch    = (bid >> 5) & 1;     // o-chunk in quarter
        const int kc    = bid & 31;           // k-split
        const int obase = q * QDIM + ch * OCH;
        const int d0    = kc * KCH;

        uint64_t acc[8];                      // 16 batch accs as f32x2
#pragma unroll
        for (int i = 0; i < 8; ++i) acc[i] = 0ull;

#pragma unroll
        for (int sc = 0; sc < NSUB; ++sc) {
            const int dd0 = d0 + sc * SUBK;

            // state subtile transposed: sS[d][b] (threads 0..127).
            if (t < 128) {
                const int b  = t >> 3;
                const int c4 = t & 7;
                const float4 v = *(const float4*)(state + b * DDIM + dd0 + c4 * 4);
                sm.s1.sS[c4 * 4 + 0][b] = v.x;
                sm.s1.sS[c4 * 4 + 1][b] = v.y;
                sm.s1.sS[c4 * 4 + 2][b] = v.z;
                sm.s1.sS[c4 * 4 + 3][b] = v.w;
            }
            // W subtile 256 rows x 32 d: 2048 float4, 8/thread, coalesced
            // (8 lanes/row, nL=4); STS banks (r + 4c4 + k) % 32 conflict-free.
#pragma unroll
            for (int j = 0; j < 8; ++j) {
                const int g  = j * 256 + t;
                const int r  = g >> 3;
                const int c4 = g & 7;
                const float4 v = *(const float4*)(W + (long)(obase + r) * DDIM
                                                  + dd0 + c4 * 4);
                sm.s1.sW[r][c4 * 4 + 0] = v.x;
                sm.s1.sW[r][c4 * 4 + 1] = v.y;
                sm.s1.sW[r][c4 * 4 + 2] = v.z;
                sm.s1.sW[r][c4 * 4 + 3] = v.w;
            }
            __syncthreads();

#pragma unroll 8
            for (int d = 0; d < SUBK; ++d) {
                const float w = sm.s1.sW[t][d];        // bank (t+d)%32
                uint64_t wp;
                asm("mov.b64 %0, {%1, %1};" : "=l"(wp) : "r"(__float_as_uint(w)));
                const ulonglong2 q0 = *(const ulonglong2*)&sm.s1.sS[d][0];
                const ulonglong2 q1 = *(const ulonglong2*)&sm.s1.sS[d][4];
                const ulonglong2 q2 = *(const ulonglong2*)&sm.s1.sS[d][8];
                const ulonglong2 q3 = *(const ulonglong2*)&sm.s1.sS[d][12];
                ffma2(acc[0], wp, q0.x);  ffma2(acc[1], wp, q0.y);
                ffma2(acc[2], wp, q1.x);  ffma2(acc[3], wp, q1.y);
                ffma2(acc[4], wp, q2.x);  ffma2(acc[5], wp, q2.y);
                ffma2(acc[6], wp, q3.x);  ffma2(acc[7], wp, q3.y);
            }
            __syncthreads();
        }

        // Store partial: 16 consecutive floats (4 STG.128), coalesced over t.
        {
            float res[16];
#pragma unroll
            for (int j = 0; j < 8; ++j)
                asm("mov.b64 {%0, %1}, %2;"
                    : "=f"(res[2 * j]), "=f"(res[2 * j + 1]) : "l"(acc[j]));
            float* dst = &g_part[q][ch][kc][t][0];
#pragma unroll
            for (int p = 0; p < 4; ++p)
                *(float4*)(dst + p * 4) =
                    make_float4(res[p * 4], res[p * 4 + 1], res[p * 4 + 2], res[p * 4 + 3]);
        }

        __threadfence();
        __syncthreads();
        if (t == 0) s_tk = atomicAdd(&g_cnt[q * NCHQ + ch], 1);
        __syncthreads();

        if (s_tk == KS - 1) {
            // Last k-split finisher reduces this o-chunk in FIXED kc order.
            const int o = obase + t;
            float v[BATCH];
            const float bo = bias[o];
#pragma unroll
            for (int b = 0; b < BATCH; ++b) v[b] = bo;
#pragma unroll 4
            for (int k2 = 0; k2 < KS; ++k2) {
                const float4* p = (const float4*)&g_part[q][ch][k2][t][0];
#pragma unroll
                for (int w4 = 0; w4 < 4; ++w4) {
                    const float4 pv = __ldcg(p + w4);
                    v[w4 * 4 + 0] += pv.x;
                    v[w4 * 4 + 1] += pv.y;
                    v[w4 * 4 + 2] += pv.z;
                    v[w4 * 4 + 3] += pv.w;
                }
            }
#pragma unroll
            for (int b = 0; b < BATCH; ++b)
                g_altered[b * DDIM + o] = v[b];

            __threadfence();            // release altered before flag
            __syncthreads();
            if (t == 0) {
                g_cnt[q * NCHQ + ch] = 0;           // self-reset
                atomicAdd(&g_flag[q], 1);           // quarter ready at ==NCHQ
            }
        }
        return;
    }

    // ================= Stage 2 consumer =================
    const int bid2   = bid - NB_S1;
    const int b      = bid2 & 15;
    const int sg     = bid2 >> 4;               // 0..127
    const int warpId = t >> 5;
    const int lane   = t & 31;
    const int s0     = sg * 16 + warpId * 2;    // 2 s-rows per warp (MLP=8)

    const float4* r0 = (const float4*)(enc + ((long)s0 * BATCH + b) * DDIM);
    const float4* r1 = r0 + (long)BATCH * DDIM / 4;

    float4 A0 = make_float4(0.f, 0.f, 0.f, 0.f);
    float4 A1 = make_float4(0.f, 0.f, 0.f, 0.f);

    for (int q = 0; q < NQ; ++q) {
        if (t == 0) {
            while (((volatile int*)g_flag)[q] < NCHQ) __nanosleep(128);
        }
        __syncthreads();                        // also protects alt reuse
        if (t < QDIM / 4)
            ((float4*)sm.alt)[t] =
                __ldcg((const float4*)(g_altered + b * DDIM + q * QDIM) + t);
        __syncthreads();

        const int qf4 = q * (QDIM / 4);
#pragma unroll
        for (int i = 0; i < QDIM / 128; ++i) {  // 4 iters, 8 loads in flight
            const int f4 = i * 32 + lane;
            const float4 e0 = __ldcs(r0 + qf4 + f4);
            const float4 e1 = __ldcs(r1 + qf4 + f4);
            const float4 a  = ((const float4*)sm.alt)[f4];
            A0.x += e0.x * a.x;  A0.y += e0.y * a.y;
            A0.z += e0.z * a.z;  A0.w += e0.w * a.w;
            A1.x += e1.x * a.x;  A1.y += e1.y * a.y;
            A1.z += e1.z * a.z;  A1.w += e1.w * a.w;
        }
    }

    float t0 = (A0.x + A0.y) + (A0.z + A0.w);
    float t1 = (A1.x + A1.y) + (A1.z + A1.w);
#pragma unroll
    for (int off = 16; off > 0; off >>= 1) {
        t0 += __shfl_down_sync(0xFFFFFFFFu, t0, off);
        t1 += __shfl_down_sync(0xFFFFFFFFu, t1, off);
    }
    if (lane == 0) {
        out[b * S_LEN + s0]     = t0;
        out[b * S_LEN + s0 + 1] = t1;
    }

    __syncthreads();
    if (t == 0) {
        const int tk = atomicAdd(&g_s2cnt, 1);
        if (tk == NS2 - 1) {                    // last consumer: self-reset
#pragma unroll
            for (int q = 0; q < NQ; ++q) g_flag[q] = 0;
            g_s2cnt = 0;
        }
    }
}

extern "C" void kernel_launch(void* const* d_in, const int* in_sizes, int n_in,
                              void* d_out, int out_size)
{
    const float* enc   = (const float*)d_in[0];  // [S, B, D]
    const float* state = (const float*)d_in[1];  // [B, D]
    const float* W     = (const float*)d_in[2];  // [D, D]
    const float* bias  = (const float*)d_in[3];  // [D]
    float* out         = (float*)d_out;          // [B, S]

    attender_fused<<<NB, 256>>>(state, W, bias, enc, out);
}